// round 1
// baseline (speedup 1.0000x reference)
#include <cuda_runtime.h>
#include <cstdint>

// Problem constants
#define B_SZ   256
#define LDIM   257                 // N+1
#define M_MAP  66049               // 257*257  (GEMM K)
#define KP     66080               // K padded to multiple of 32 (32*2065)
#define H_DIM  512
#define C_OUT  4

// GEMM tiling
#define BM 128
#define BN 64
#define BK 32
#define SPLITS 59                  // 2065 = 59 * 35 chunks of BK
#define CPS 35

// Scratch (static device allocations are allowed)
__device__ __align__(16) float g_A[(size_t)B_SZ * KP];                  // ~67.7 MB, tf32-rounded activations
__device__ __align__(16) float g_part[(size_t)SPLITS * B_SZ * H_DIM];   // ~30.9 MB, split-K partials
__device__ float g_consts[5];                                           // folded conv+BN

__device__ __forceinline__ float frcp(float x) {
    float r; asm("rcp.approx.f32 %0, %1;" : "=f"(r) : "f"(x)); return r;
}
__device__ __forceinline__ uint32_t f2tf32(float x) {
    uint32_t u; asm("cvt.rna.tf32.f32 %0, %1;" : "=r"(u) : "f"(x)); return u;
}

// ---------------------------------------------------------------------------
// Phase 0: fold 1x1-conv + eval-mode BN into 4 weights + 1 bias
// ---------------------------------------------------------------------------
__global__ void prep_kernel(const float* __restrict__ conv_w, const float* __restrict__ conv_b,
                            const float* __restrict__ bn_g,  const float* __restrict__ bn_b,
                            const float* __restrict__ bn_m,  const float* __restrict__ bn_v) {
    if (threadIdx.x == 0) {
        float s = bn_g[0] * rsqrtf(bn_v[0] + 1e-5f);
        g_consts[0] = conv_w[0] * s;
        g_consts[1] = conv_w[1] * s;
        g_consts[2] = conv_w[2] * s;
        g_consts[3] = conv_w[3] * s;
        g_consts[4] = (conv_b[0] - bn_m[0]) * s + bn_b[0];
    }
}

// ---------------------------------------------------------------------------
// Phase 1: activation map A[b, i*257+j] = leaky(affine(sum_c w_c * map_c))
// One block per (b, i) row; 257 j-elements per block.
// sigmoid(x) = 1/(1+exp(-x)); x_div's outer leaky is identity (sigmoid >= 0).
// ---------------------------------------------------------------------------
__global__ void act_kernel(const float* __restrict__ x1, const float* __restrict__ x3) {
    const int bi = blockIdx.x;
    const int b  = bi / LDIM;
    const int i  = bi - b * LDIM;

    const float b0 = (i == 0) ? 0.0f : x3[i - 1];
    const float b1 = (i == 0) ? 1.0f : b0;
    const float Eb = __expf(-b0);                       // e^{-b0}

    const float c0 = g_consts[0], c1 = g_consts[1];
    const float c2 = g_consts[2], c3 = g_consts[3];
    const float cb = g_consts[4];

    const float* __restrict__ x1r = x1 + b * (LDIM - 1);
    float* __restrict__ arow = g_A + (size_t)b * KP + (size_t)i * LDIM;

    for (int j = threadIdx.x; j < LDIM; j += blockDim.x) {
        const float a0 = (j == 0) ? 0.0f : x1r[j - 1];
        const float a1 = (j == 0) ? 1.0f : a0;

        const float Ea = __expf(-a0);                   // e^{-a0}
        const float Pa = frcp(Ea);                      // e^{+a0}
        const float xadd = frcp(1.0f + Eb * Ea);        // sigmoid(b0 + a0)
        const float xsub = frcp(1.0f + Eb * Pa);        // sigmoid(b0 - a0)
        const float xpro = frcp(1.0f + __expf(-b1 * a1));                    // sigmoid(b1*a1)
        const float xdiv = frcp(1.0f + __expf(-b1 * frcp(a1 + 1e-10f)));     // sigmoid(b1/(a1+eps))

        float y = c0 * xadd + c1 * xsub + c2 * xpro + c3 * xdiv + cb;
        y = (y >= 0.0f) ? y : 0.1f * y;                 // leaky
        arow[j] = __uint_as_float(f2tf32(y));           // pre-round to tf32
    }

    // zero the K padding tail [66049, 66080) once per batch row
    if (i == 0) {
        for (int t = threadIdx.x; t < KP - M_MAP; t += blockDim.x)
            g_A[(size_t)b * KP + M_MAP + t] = 0.0f;
    }
}

// ---------------------------------------------------------------------------
// Phase 2: split-K tf32 GEMM  out1[b,h] = sum_k A[b,k] * fc_w[h,k]
// mma.sync.aligned.m16n8k8 tf32, 256 threads, 4x2 warps, 32x32 warp tiles.
// Deterministic: partials go to g_part, reduced in phase 3.
// ---------------------------------------------------------------------------
__device__ __forceinline__ void mma_tf32(float c[4], const uint32_t a[4], const uint32_t b[2]) {
    asm volatile(
        "mma.sync.aligned.m16n8k8.row.col.f32.tf32.tf32.f32 "
        "{%0,%1,%2,%3}, {%4,%5,%6,%7}, {%8,%9}, {%0,%1,%2,%3};\n"
        : "+f"(c[0]), "+f"(c[1]), "+f"(c[2]), "+f"(c[3])
        : "r"(a[0]), "r"(a[1]), "r"(a[2]), "r"(a[3]), "r"(b[0]), "r"(b[1]));
}

__global__ void __launch_bounds__(256, 2) gemm_kernel(const float* __restrict__ W) {
    __shared__ __align__(16) uint32_t As[BM][BK + 4];   // row stride 36 floats (conflict-free)
    __shared__ __align__(16) uint32_t Bs[BN][BK + 4];

    const int tile  = blockIdx.x;            // 16 (M,N) tiles
    const int bm0   = (tile & 1) * BM;
    const int bn0   = (tile >> 1) * BN;
    const int split = blockIdx.y;            // 59 K-splits

    const int tid  = threadIdx.x;
    const int wid  = tid >> 5, lane = tid & 31;
    const int wm   = wid & 3,  wn   = wid >> 2;   // 4 x 2 warp grid
    const int g    = lane >> 2, tg  = lane & 3;

    float acc[2][4][4];
#pragma unroll
    for (int mi = 0; mi < 2; mi++)
#pragma unroll
        for (int ni = 0; ni < 4; ni++)
#pragma unroll
            for (int q = 0; q < 4; q++) acc[mi][ni][q] = 0.0f;

    const int cbeg = split * CPS;
    for (int c = cbeg; c < cbeg + CPS; ++c) {
        const int k0 = c * BK;

        // Load A tile (128x32 fp32, already tf32-rounded): 4 float4 per thread
#pragma unroll
        for (int r = 0; r < 4; r++) {
            int flat = tid + r * 256;            // float4 index 0..1023
            int m = flat >> 3, kq = flat & 7;
            const float4 v = *reinterpret_cast<const float4*>(
                &g_A[(size_t)(bm0 + m) * KP + k0 + kq * 4]);
            *reinterpret_cast<float4*>(&As[m][kq * 4]) = v;
        }
        // Load W tile (64x32 fp32 -> tf32): 8 scalars per thread, coalesced per warp
#pragma unroll
        for (int r = 0; r < 8; r++) {
            int flat = tid + r * 256;
            int n = flat >> 5, k = flat & 31;
            int kk = k0 + k;
            float v = (kk < M_MAP) ? W[(size_t)(bn0 + n) * M_MAP + kk] : 0.0f;
            Bs[n][k] = f2tf32(v);
        }
        __syncthreads();

#pragma unroll
        for (int ks = 0; ks < 4; ++ks) {         // four k8 steps
            uint32_t a[2][4], bf[4][2];
#pragma unroll
            for (int mi = 0; mi < 2; mi++) {
                int r0 = wm * 32 + mi * 16 + g;
                a[mi][0] = As[r0    ][ks * 8 + tg];
                a[mi][1] = As[r0 + 8][ks * 8 + tg];
                a[mi][2] = As[r0    ][ks * 8 + tg + 4];
                a[mi][3] = As[r0 + 8][ks * 8 + tg + 4];
            }
#pragma unroll
            for (int ni = 0; ni < 4; ni++) {
                int n0 = wn * 32 + ni * 8 + g;
                bf[ni][0] = Bs[n0][ks * 8 + tg];
                bf[ni][1] = Bs[n0][ks * 8 + tg + 4];
            }
#pragma unroll
            for (int mi = 0; mi < 2; mi++)
#pragma unroll
                for (int ni = 0; ni < 4; ni++)
                    mma_tf32(acc[mi][ni], a[mi], bf[ni]);
        }
        __syncthreads();
    }

    // Write split partials (plain stores: deterministic)
    float* __restrict__ P = g_part + (size_t)split * (B_SZ * H_DIM);
#pragma unroll
    for (int mi = 0; mi < 2; mi++) {
#pragma unroll
        for (int ni = 0; ni < 4; ni++) {
            int row = bm0 + wm * 32 + mi * 16 + g;
            int col = bn0 + wn * 32 + ni * 8 + tg * 2;
            *reinterpret_cast<float2*>(&P[(size_t)row * H_DIM + col]) =
                make_float2(acc[mi][ni][0], acc[mi][ni][1]);
            *reinterpret_cast<float2*>(&P[(size_t)(row + 8) * H_DIM + col]) =
                make_float2(acc[mi][ni][2], acc[mi][ni][3]);
        }
    }
}

// ---------------------------------------------------------------------------
// Phase 3: reduce splits + fc_b -> ReLU -> (512 -> 4) head GEMV
// ---------------------------------------------------------------------------
__global__ void head_kernel(const float* __restrict__ fc_b,
                            const float* __restrict__ out_w,
                            const float* __restrict__ out_b,
                            float* __restrict__ out) {
    const int b = blockIdx.x;        // 256
    const int tid = threadIdx.x;     // 128

    float s[4] = {0.f, 0.f, 0.f, 0.f};
    for (int h = tid; h < H_DIM; h += 128) {
        float v = 0.0f;
        for (int sp = 0; sp < SPLITS; ++sp)
            v += g_part[(size_t)sp * (B_SZ * H_DIM) + (size_t)b * H_DIM + h];
        v += fc_b[h];
        v = fmaxf(v, 0.0f);
#pragma unroll
        for (int cc = 0; cc < 4; ++cc) s[cc] += v * out_w[cc * H_DIM + h];
    }
#pragma unroll
    for (int off = 16; off > 0; off >>= 1)
#pragma unroll
        for (int cc = 0; cc < 4; ++cc) s[cc] += __shfl_down_sync(0xffffffffu, s[cc], off);

    __shared__ float red[4][4];
    if ((tid & 31) == 0) {
#pragma unroll
        for (int cc = 0; cc < 4; ++cc) red[cc][tid >> 5] = s[cc];
    }
    __syncthreads();
    if (tid < 4) {
        float r = red[tid][0] + red[tid][1] + red[tid][2] + red[tid][3];
        out[b * C_OUT + tid] = r + out_b[tid];
    }
}

// ---------------------------------------------------------------------------
extern "C" void kernel_launch(void* const* d_in, const int* in_sizes, int n_in,
                              void* d_out, int out_size) {
    const float* x1     = (const float*)d_in[0];
    const float* x3     = (const float*)d_in[1];
    const float* conv_w = (const float*)d_in[2];
    const float* conv_b = (const float*)d_in[3];
    const float* bn_g   = (const float*)d_in[4];
    const float* bn_b   = (const float*)d_in[5];
    const float* bn_m   = (const float*)d_in[6];
    const float* bn_v   = (const float*)d_in[7];
    const float* fc_w   = (const float*)d_in[8];
    const float* fc_b   = (const float*)d_in[9];
    const float* out_w  = (const float*)d_in[10];
    const float* out_b  = (const float*)d_in[11];
    float* out = (float*)d_out;

    prep_kernel<<<1, 32>>>(conv_w, conv_b, bn_g, bn_b, bn_m, bn_v);
    act_kernel<<<B_SZ * LDIM, 256>>>(x1, x3);
    dim3 grid(16, SPLITS);
    gemm_kernel<<<grid, 256>>>(fc_w);
    head_kernel<<<B_SZ, 128>>>(fc_b, out_w, out_b, out);
}

// round 4
// speedup vs baseline: 1.2975x; 1.2975x over previous
#include <cuda_runtime.h>
#include <cstdint>

// Problem constants
#define B_SZ   256
#define LDIM   257                 // N+1
#define M_MAP  66049               // 257*257  (GEMM K)
#define KP     66080               // K padded to multiple of 32
#define H_DIM  512
#define C_OUT  4

// GEMM tiling
#define BM 256                     // full batch -> fc_w read exactly once
#define BN 128                     // 4 N tiles  -> A read 4x
#define BK 16
#define SPLITS 35                  // 4130 k16-chunks = 35 * 118
#define CPS 118

// smem geometry (floats). Row stride 20: conflict-free frag LDS, 16B aligned.
#define ROWSTR 20
#define AS_FLOATS (BM * ROWSTR)                 // 5120
#define STAGE_FLOATS (AS_FLOATS + BN * ROWSTR)  // 7680
#define STAGES 3
#define SMEM_BYTES (STAGES * STAGE_FLOATS * 4)  // 92160

// Scratch
__device__ __align__(16) float g_A[(size_t)B_SZ * KP];                  // ~67.7 MB tf32-rounded activations
__device__ __align__(16) float g_part[(size_t)SPLITS * B_SZ * H_DIM];   // ~18.4 MB split-K partials
__device__ float g_consts[5];

__device__ __forceinline__ float frcp(float x) {
    float r; asm("rcp.approx.f32 %0, %1;" : "=f"(r) : "f"(x)); return r;
}
__device__ __forceinline__ uint32_t f2tf32(float x) {
    uint32_t u; asm("cvt.rna.tf32.f32 %0, %1;" : "=r"(u) : "f"(x)); return u;
}
__device__ __forceinline__ uint32_t smem_u32(const void* p) {
    return (uint32_t)__cvta_generic_to_shared(p);
}
__device__ __forceinline__ void cp16(uint32_t dst, const float* src) {
    asm volatile("cp.async.cg.shared.global [%0], [%1], 16;\n" :: "r"(dst), "l"(src));
}
// 4-byte cp.async (always aligned for fp32); src_bytes 0 -> zero-fill
__device__ __forceinline__ void cp4z(uint32_t dst, const float* src, int src_bytes) {
    asm volatile("cp.async.ca.shared.global [%0], [%1], 4, %2;\n" :: "r"(dst), "l"(src), "r"(src_bytes));
}

// ---------------------------------------------------------------------------
// Phase 0: fold conv + BN
// ---------------------------------------------------------------------------
__global__ void prep_kernel(const float* __restrict__ conv_w, const float* __restrict__ conv_b,
                            const float* __restrict__ bn_g,  const float* __restrict__ bn_b,
                            const float* __restrict__ bn_m,  const float* __restrict__ bn_v) {
    if (threadIdx.x == 0) {
        float s = bn_g[0] * rsqrtf(bn_v[0] + 1e-5f);
        g_consts[0] = conv_w[0] * s;
        g_consts[1] = conv_w[1] * s;
        g_consts[2] = conv_w[2] * s;
        g_consts[3] = conv_w[3] * s;
        g_consts[4] = (conv_b[0] - bn_m[0]) * s + bn_b[0];
    }
}

// ---------------------------------------------------------------------------
// Phase 1: activations, j-dependent transcendentals hoisted to smem.
// ---------------------------------------------------------------------------
__global__ void __launch_bounds__(256) act_kernel(const float* __restrict__ x1,
                                                  const float* __restrict__ x3) {
    const int b    = blockIdx.x >> 1;
    const int half = blockIdx.x & 1;
    const int i0 = half ? 129 : 0;
    const int i1 = half ? LDIM : 129;

    __shared__ float sEa[LDIM], sPa[LDIM], sA1[LDIM], sRa[LDIM];

    for (int j = threadIdx.x; j < LDIM; j += 256) {
        const float a0 = (j == 0) ? 0.0f : x1[b * (LDIM - 1) + j - 1];
        const float a1 = (j == 0) ? 1.0f : a0;
        const float Ea = __expf(-a0);
        sEa[j] = Ea;
        sPa[j] = frcp(Ea);
        sA1[j] = a1;
        sRa[j] = frcp(a1 + 1e-10f);
    }
    __syncthreads();

    const float c0 = g_consts[0], c1 = g_consts[1];
    const float c2 = g_consts[2], c3 = g_consts[3];
    const float cb = g_consts[4];

    for (int i = i0; i < i1; ++i) {
        const float b0 = (i == 0) ? 0.0f : x3[i - 1];
        const float b1 = (i == 0) ? 1.0f : b0;
        const float Eb = __expf(-b0);
        float* __restrict__ row = g_A + (size_t)b * KP + (size_t)i * LDIM;

        for (int j = threadIdx.x; j < LDIM; j += 256) {
            const float xadd = frcp(1.0f + Eb * sEa[j]);
            const float xsub = frcp(1.0f + Eb * sPa[j]);
            const float xpro = frcp(1.0f + __expf(-b1 * sA1[j]));
            const float xdiv = frcp(1.0f + __expf(-b1 * sRa[j]));
            float y = c0 * xadd + c1 * xsub + c2 * xpro + c3 * xdiv + cb;
            y = (y >= 0.0f) ? y : 0.1f * y;
            row[j] = __uint_as_float(f2tf32(y));
        }
    }

    if (half == 0 && threadIdx.x < KP - M_MAP)
        g_A[(size_t)b * KP + M_MAP + threadIdx.x] = 0.0f;
}

// ---------------------------------------------------------------------------
// Phase 2: split-K tf32 GEMM, cp.async 3-stage pipeline.
// 512 threads, 4x4 warp grid, warp tile 64x32.
// A tile: 16B cp.async (g_A rows are 16B aligned).
// B tile: 4B cp.async (fc_w row stride 66049 floats is odd -> only 4B aligned!).
// ---------------------------------------------------------------------------
__device__ __forceinline__ void mma_tf32(float c[4], const uint32_t a[4], const uint32_t b[2]) {
    asm volatile(
        "mma.sync.aligned.m16n8k8.row.col.f32.tf32.tf32.f32 "
        "{%0,%1,%2,%3}, {%4,%5,%6,%7}, {%8,%9}, {%0,%1,%2,%3};\n"
        : "+f"(c[0]), "+f"(c[1]), "+f"(c[2]), "+f"(c[3])
        : "r"(a[0]), "r"(a[1]), "r"(a[2]), "r"(a[3]), "r"(b[0]), "r"(b[1]));
}

__device__ __forceinline__ void load_chunk(float* sm, int stage, int gchunk, int bn0,
                                           const float* __restrict__ W, int tid) {
    const int k0 = gchunk * BK;
    float* S = sm + stage * STAGE_FLOATS;

    // A tile: 256x16 floats = 1024 float4, 2 per thread (aligned: KP stride, k0 mult of 16)
#pragma unroll
    for (int r = 0; r < 2; r++) {
        int flat = tid + r * 512;
        int m = flat >> 2, kq = flat & 3;
        cp16(smem_u32(&S[m * ROWSTR + kq * 4]),
             &g_A[(size_t)m * KP + k0 + kq * 4]);
    }
    // B tile: 128x16 floats = 2048 scalars, 4 per thread, 4B cp.async (alignment-safe)
#pragma unroll
    for (int r = 0; r < 4; r++) {
        int flat = tid + r * 512;
        int n = flat >> 4, k = flat & 15;
        int ke = k0 + k;
        int bytes = (ke < M_MAP) ? 4 : 0;
        const float* src = &W[(size_t)(bn0 + n) * M_MAP + (bytes ? ke : 0)];
        cp4z(smem_u32(&S[AS_FLOATS + n * ROWSTR + k]), src, bytes);
    }
}

__global__ void __launch_bounds__(512, 1) gemm_kernel(const float* __restrict__ W) {
    extern __shared__ float sm[];

    const int bn0   = blockIdx.x * BN;     // 4 N tiles
    const int split = blockIdx.y;          // 35 K splits
    const int cbeg  = split * CPS;

    const int tid  = threadIdx.x;
    const int wid  = tid >> 5, lane = tid & 31;
    const int wm   = wid & 3,  wn   = wid >> 2;    // 4 x 4
    const int g    = lane >> 2, tg  = lane & 3;

    float acc[4][4][4];
#pragma unroll
    for (int mi = 0; mi < 4; mi++)
#pragma unroll
        for (int ni = 0; ni < 4; ni++)
#pragma unroll
            for (int q = 0; q < 4; q++) acc[mi][ni][q] = 0.0f;

    load_chunk(sm, 0, cbeg + 0, bn0, W, tid);
    asm volatile("cp.async.commit_group;\n" ::: "memory");
    load_chunk(sm, 1, cbeg + 1, bn0, W, tid);
    asm volatile("cp.async.commit_group;\n" ::: "memory");

    for (int cc = 0; cc < CPS; ++cc) {
        asm volatile("cp.async.wait_group 1;\n" ::: "memory");
        __syncthreads();

        if (cc + 2 < CPS)
            load_chunk(sm, (cc + 2) % STAGES, cbeg + cc + 2, bn0, W, tid);
        asm volatile("cp.async.commit_group;\n" ::: "memory");

        const float* Sa = sm + (cc % STAGES) * STAGE_FLOATS;
        const float* Sb = Sa + AS_FLOATS;

#pragma unroll
        for (int ks = 0; ks < 2; ++ks) {
            uint32_t a[4][4], bfr[4][2];
#pragma unroll
            for (int mi = 0; mi < 4; mi++) {
                const int r0 = wm * 64 + mi * 16 + g;
                a[mi][0] = __float_as_uint(Sa[(r0    ) * ROWSTR + ks * 8 + tg]);
                a[mi][1] = __float_as_uint(Sa[(r0 + 8) * ROWSTR + ks * 8 + tg]);
                a[mi][2] = __float_as_uint(Sa[(r0    ) * ROWSTR + ks * 8 + tg + 4]);
                a[mi][3] = __float_as_uint(Sa[(r0 + 8) * ROWSTR + ks * 8 + tg + 4]);
            }
#pragma unroll
            for (int ni = 0; ni < 4; ni++) {
                const int n0 = wn * 32 + ni * 8 + g;
                bfr[ni][0] = f2tf32(Sb[n0 * ROWSTR + ks * 8 + tg]);
                bfr[ni][1] = f2tf32(Sb[n0 * ROWSTR + ks * 8 + tg + 4]);
            }
#pragma unroll
            for (int mi = 0; mi < 4; mi++)
#pragma unroll
                for (int ni = 0; ni < 4; ni++)
                    mma_tf32(acc[mi][ni], a[mi], bfr[ni]);
        }
    }

    // Deterministic partial store
    float* __restrict__ P = g_part + (size_t)split * (B_SZ * H_DIM);
#pragma unroll
    for (int mi = 0; mi < 4; mi++) {
#pragma unroll
        for (int ni = 0; ni < 4; ni++) {
            const int row = wm * 64 + mi * 16 + g;
            const int col = bn0 + wn * 32 + ni * 8 + tg * 2;
            *reinterpret_cast<float2*>(&P[(size_t)row * H_DIM + col]) =
                make_float2(acc[mi][ni][0], acc[mi][ni][1]);
            *reinterpret_cast<float2*>(&P[(size_t)(row + 8) * H_DIM + col]) =
                make_float2(acc[mi][ni][2], acc[mi][ni][3]);
        }
    }
}

// ---------------------------------------------------------------------------
// Phase 3: reduce splits + bias -> ReLU -> 512->4 head
// ---------------------------------------------------------------------------
__global__ void __launch_bounds__(512) head_kernel(const float* __restrict__ fc_b,
                                                   const float* __restrict__ out_w,
                                                   const float* __restrict__ out_b,
                                                   float* __restrict__ out) {
    const int b = blockIdx.x;
    const int h = threadIdx.x;          // 512 threads = one per hidden unit
    const int wid = h >> 5, lane = h & 31;

    float v = 0.0f;
#pragma unroll
    for (int sp = 0; sp < SPLITS; ++sp)
        v += g_part[(size_t)sp * (B_SZ * H_DIM) + (size_t)b * H_DIM + h];
    v += fc_b[h];
    v = fmaxf(v, 0.0f);

    float p[4];
#pragma unroll
    for (int c = 0; c < 4; ++c) p[c] = v * out_w[c * H_DIM + h];

#pragma unroll
    for (int off = 16; off > 0; off >>= 1)
#pragma unroll
        for (int c = 0; c < 4; ++c) p[c] += __shfl_down_sync(0xffffffffu, p[c], off);

    __shared__ float red[4][16];
    if (lane == 0) {
#pragma unroll
        for (int c = 0; c < 4; ++c) red[c][wid] = p[c];
    }
    __syncthreads();
    if (h < 4) {
        float s = 0.0f;
#pragma unroll
        for (int w = 0; w < 16; ++w) s += red[h][w];
        out[b * C_OUT + h] = s + out_b[h];
    }
}

// ---------------------------------------------------------------------------
extern "C" void kernel_launch(void* const* d_in, const int* in_sizes, int n_in,
                              void* d_out, int out_size) {
    const float* x1     = (const float*)d_in[0];
    const float* x3     = (const float*)d_in[1];
    const float* conv_w = (const float*)d_in[2];
    const float* conv_b = (const float*)d_in[3];
    const float* bn_g   = (const float*)d_in[4];
    const float* bn_b   = (const float*)d_in[5];
    const float* bn_m   = (const float*)d_in[6];
    const float* bn_v   = (const float*)d_in[7];
    const float* fc_w   = (const float*)d_in[8];
    const float* fc_b   = (const float*)d_in[9];
    const float* out_w  = (const float*)d_in[10];
    const float* out_b  = (const float*)d_in[11];
    float* out = (float*)d_out;

    cudaFuncSetAttribute(gemm_kernel, cudaFuncAttributeMaxDynamicSharedMemorySize, SMEM_BYTES);

    prep_kernel<<<1, 32>>>(conv_w, conv_b, bn_g, bn_b, bn_m, bn_v);
    act_kernel<<<B_SZ * 2, 256>>>(x1, x3);
    dim3 grid(H_DIM / BN, SPLITS);
    gemm_kernel<<<grid, 512, SMEM_BYTES>>>(fc_w);
    head_kernel<<<B_SZ, 512>>>(fc_b, out_w, out_b, out);
}

// round 9
// speedup vs baseline: 1.7841x; 1.3750x over previous
#include <cuda_runtime.h>
#include <cuda_fp16.h>
#include <cstdint>

// Problem constants
#define B_SZ   256
#define LDIM   257                 // N+1
#define M_MAP  66049               // 257*257  (GEMM K)
#define KP     66080               // K padded to multiple of 32
#define H_DIM  512
#define C_OUT  4

// GEMM tiling (legacy fp16 mma m16n8k16)
#define BM 256                     // full batch
#define BN 128                     // 4 N tiles
#define BK 32                      // 2 k16 steps per chunk
#define SPLITS 35                  // 2065 k32-chunks = 35 * 59
#define CPS 59

// smem geometry
#define AROW 40                    // halfs per A row (32 + 8 pad) = 80B, 16B aligned
#define BROW 36                    // floats per B row (32 + 4 pad) = 144B
#define STAGE_BYTES (BM * AROW * 2 + BN * BROW * 4)   // 20480 + 18432 = 38912
#define STAGES 3
#define SMEM_BYTES (STAGES * STAGE_BYTES)       // 116736

// Scratch
__device__ __align__(16) __half g_A[(size_t)B_SZ * KP];                // ~33.8 MB fp16 activations
__device__ __align__(16) float g_part[(size_t)SPLITS * B_SZ * H_DIM];  // ~18.4 MB split-K partials
__device__ float g_consts[5];

__device__ __forceinline__ float frcp(float x) {
    float r; asm("rcp.approx.f32 %0, %1;" : "=f"(r) : "f"(x)); return r;
}
__device__ __forceinline__ uint32_t smem_u32(const void* p) {
    return (uint32_t)__cvta_generic_to_shared(p);
}
__device__ __forceinline__ void cp16(uint32_t dst, const void* src) {
    asm volatile("cp.async.cg.shared.global [%0], [%1], 16;\n" :: "r"(dst), "l"(src));
}
// 4-byte cp.async (fp32-safe alignment); src_bytes 0 -> zero-fill
__device__ __forceinline__ void cp4z(uint32_t dst, const float* src, int src_bytes) {
    asm volatile("cp.async.ca.shared.global [%0], [%1], 4, %2;\n" :: "r"(dst), "l"(src), "r"(src_bytes));
}
// pack two fp32 -> half2 (rn) as u32
__device__ __forceinline__ uint32_t pack_h2(float lo, float hi) {
    uint32_t u;
    asm("cvt.rn.f16x2.f32 %0, %1, %2;" : "=r"(u) : "f"(hi), "f"(lo));
    return u;
}

// ---------------------------------------------------------------------------
// Phase 0: fold 1x1-conv + eval-mode BN
// ---------------------------------------------------------------------------
__global__ void prep_kernel(const float* __restrict__ conv_w, const float* __restrict__ conv_b,
                            const float* __restrict__ bn_g,  const float* __restrict__ bn_b,
                            const float* __restrict__ bn_m,  const float* __restrict__ bn_v) {
    if (threadIdx.x == 0) {
        float s = bn_g[0] * rsqrtf(bn_v[0] + 1e-5f);
        g_consts[0] = conv_w[0] * s;
        g_consts[1] = conv_w[1] * s;
        g_consts[2] = conv_w[2] * s;
        g_consts[3] = conv_w[3] * s;
        g_consts[4] = (conv_b[0] - bn_m[0]) * s + bn_b[0];
    }
}

// ---------------------------------------------------------------------------
// Phase 1: activation map -> fp16 (10-bit mantissa, same rounding as tf32)
// ---------------------------------------------------------------------------
__global__ void __launch_bounds__(256) act_kernel(const float* __restrict__ x1,
                                                  const float* __restrict__ x3) {
    const int b    = blockIdx.x >> 1;
    const int half = blockIdx.x & 1;
    const int i0 = half ? 129 : 0;
    const int i1 = half ? LDIM : 129;

    __shared__ float sEa[LDIM], sPa[LDIM], sA1[LDIM], sRa[LDIM];

    for (int j = threadIdx.x; j < LDIM; j += 256) {
        const float a0 = (j == 0) ? 0.0f : x1[b * (LDIM - 1) + j - 1];
        const float a1 = (j == 0) ? 1.0f : a0;
        const float Ea = __expf(-a0);
        sEa[j] = Ea;
        sPa[j] = frcp(Ea);
        sA1[j] = a1;
        sRa[j] = frcp(a1 + 1e-10f);
    }
    __syncthreads();

    const float c0 = g_consts[0], c1 = g_consts[1];
    const float c2 = g_consts[2], c3 = g_consts[3];
    const float cb = g_consts[4];

    for (int i = i0; i < i1; ++i) {
        const float b0 = (i == 0) ? 0.0f : x3[i - 1];
        const float b1 = (i == 0) ? 1.0f : b0;
        const float Eb = __expf(-b0);
        __half* __restrict__ row = g_A + (size_t)b * KP + (size_t)i * LDIM;

        for (int j = threadIdx.x; j < LDIM; j += 256) {
            const float xadd = frcp(1.0f + Eb * sEa[j]);
            const float xsub = frcp(1.0f + Eb * sPa[j]);
            const float xpro = frcp(1.0f + __expf(-b1 * sA1[j]));
            const float xdiv = frcp(1.0f + __expf(-b1 * sRa[j]));
            float y = c0 * xadd + c1 * xsub + c2 * xpro + c3 * xdiv + cb;
            y = (y >= 0.0f) ? y : 0.1f * y;
            row[j] = __float2half_rn(y);
        }
    }

    if (half == 0 && threadIdx.x < KP - M_MAP)
        g_A[(size_t)b * KP + M_MAP + threadIdx.x] = __float2half_rn(0.0f);
}

// ---------------------------------------------------------------------------
// Phase 2: split-K fp16 GEMM (m16n8k16, fp32 accumulate), cp.async 3-stage.
// 512 threads, 4x4 warp grid, warp tile 64x32.
// ---------------------------------------------------------------------------
__device__ __forceinline__ void mma_f16(float c[4], const uint32_t a[4], const uint32_t b[2]) {
    asm volatile(
        "mma.sync.aligned.m16n8k16.row.col.f32.f16.f16.f32 "
        "{%0,%1,%2,%3}, {%4,%5,%6,%7}, {%8,%9}, {%0,%1,%2,%3};\n"
        : "+f"(c[0]), "+f"(c[1]), "+f"(c[2]), "+f"(c[3])
        : "r"(a[0]), "r"(a[1]), "r"(a[2]), "r"(a[3]), "r"(b[0]), "r"(b[1]));
}

__device__ __forceinline__ void load_chunk(char* sm, int stage, int gchunk, int bn0,
                                           const float* __restrict__ W, int tid) {
    const int k0 = gchunk * BK;
    char* S = sm + stage * STAGE_BYTES;
    uint32_t sA = smem_u32(S);                        // A: BM x AROW halfs
    uint32_t sB = smem_u32(S + BM * AROW * 2);        // B: BN x BROW floats

    // A tile: 256 rows x 32 halfs = 64B/row = 4x16B; 1024 cp16, 2 per thread
#pragma unroll
    for (int r = 0; r < 2; r++) {
        int flat = tid + r * 512;
        int m = flat >> 2, q = flat & 3;              // q: 16B quarter (8 halfs)
        cp16(sA + m * (AROW * 2) + q * 16,
             &g_A[(size_t)m * KP + k0 + q * 8]);
    }
    // B tile: 128 rows x 32 floats = 4096 scalars, 8 per thread (4B, alignment-safe)
#pragma unroll
    for (int r = 0; r < 8; r++) {
        int flat = tid + r * 512;
        int n = flat >> 5, k = flat & 31;
        int ke = k0 + k;
        int bytes = (ke < M_MAP) ? 4 : 0;
        const float* src = &W[(size_t)(bn0 + n) * M_MAP + (bytes ? ke : 0)];
        cp4z(sB + (n * BROW + k) * 4, src, bytes);
    }
}

__global__ void __launch_bounds__(512, 1) gemm_kernel(const float* __restrict__ W) {
    extern __shared__ char sm[];

    const int bn0   = blockIdx.x * BN;     // 4 N tiles
    const int split = blockIdx.y;          // 35 K splits
    const int cbeg  = split * CPS;

    const int tid  = threadIdx.x;
    const int wid  = tid >> 5, lane = tid & 31;
    const int wm   = wid & 3,  wn   = wid >> 2;    // 4 x 4
    const int g    = lane >> 2, tg  = lane & 3;

    float acc[4][4][4];
#pragma unroll
    for (int mi = 0; mi < 4; mi++)
#pragma unroll
        for (int ni = 0; ni < 4; ni++)
#pragma unroll
            for (int q = 0; q < 4; q++) acc[mi][ni][q] = 0.0f;

    load_chunk(sm, 0, cbeg + 0, bn0, W, tid);
    asm volatile("cp.async.commit_group;\n" ::: "memory");
    load_chunk(sm, 1, cbeg + 1, bn0, W, tid);
    asm volatile("cp.async.commit_group;\n" ::: "memory");

    for (int cc = 0; cc < CPS; ++cc) {
        asm volatile("cp.async.wait_group 1;\n" ::: "memory");
        __syncthreads();

        if (cc + 2 < CPS)
            load_chunk(sm, (cc + 2) % STAGES, cbeg + cc + 2, bn0, W, tid);
        asm volatile("cp.async.commit_group;\n" ::: "memory");

        char* S = sm + (cc % STAGES) * STAGE_BYTES;
        const __half* Sa = reinterpret_cast<const __half*>(S);
        const float*  Sb = reinterpret_cast<const float*>(S + BM * AROW * 2);

#pragma unroll
        for (int ks = 0; ks < 2; ++ks) {               // two k16 steps
            uint32_t a[4][4], bfr[4][2];
#pragma unroll
            for (int mi = 0; mi < 4; mi++) {
                const int r0 = wm * 64 + mi * 16 + g;
                const int kb = ks * 16 + tg * 2;
                a[mi][0] = *reinterpret_cast<const uint32_t*>(&Sa[(r0    ) * AROW + kb]);
                a[mi][1] = *reinterpret_cast<const uint32_t*>(&Sa[(r0 + 8) * AROW + kb]);
                a[mi][2] = *reinterpret_cast<const uint32_t*>(&Sa[(r0    ) * AROW + kb + 8]);
                a[mi][3] = *reinterpret_cast<const uint32_t*>(&Sa[(r0 + 8) * AROW + kb + 8]);
            }
#pragma unroll
            for (int ni = 0; ni < 4; ni++) {
                const int n0 = wn * 32 + ni * 8 + g;
                const int kb = ks * 16 + tg * 2;
                const float2 f01 = *reinterpret_cast<const float2*>(&Sb[n0 * BROW + kb]);
                const float2 f23 = *reinterpret_cast<const float2*>(&Sb[n0 * BROW + kb + 8]);
                bfr[ni][0] = pack_h2(f01.x, f01.y);
                bfr[ni][1] = pack_h2(f23.x, f23.y);
            }
#pragma unroll
            for (int mi = 0; mi < 4; mi++)
#pragma unroll
                for (int ni = 0; ni < 4; ni++)
                    mma_f16(acc[mi][ni], a[mi], bfr[ni]);
        }
    }

    // Deterministic partial store
    float* __restrict__ P = g_part + (size_t)split * (B_SZ * H_DIM);
#pragma unroll
    for (int mi = 0; mi < 4; mi++) {
#pragma unroll
        for (int ni = 0; ni < 4; ni++) {
            const int row = wm * 64 + mi * 16 + g;
            const int col = bn0 + wn * 32 + ni * 8 + tg * 2;
            *reinterpret_cast<float2*>(&P[(size_t)row * H_DIM + col]) =
                make_float2(acc[mi][ni][0], acc[mi][ni][1]);
            *reinterpret_cast<float2*>(&P[(size_t)(row + 8) * H_DIM + col]) =
                make_float2(acc[mi][ni][2], acc[mi][ni][3]);
        }
    }
}

// ---------------------------------------------------------------------------
// Phase 3: reduce 35 splits + bias -> ReLU -> 512->4 head
// ---------------------------------------------------------------------------
__global__ void __launch_bounds__(512) head_kernel(const float* __restrict__ fc_b,
                                                   const float* __restrict__ out_w,
                                                   const float* __restrict__ out_b,
                                                   float* __restrict__ out) {
    const int b = blockIdx.x;
    const int h = threadIdx.x;
    const int wid = h >> 5, lane = h & 31;

    float v = 0.0f;
#pragma unroll
    for (int sp = 0; sp < SPLITS; ++sp)
        v += g_part[(size_t)sp * (B_SZ * H_DIM) + (size_t)b * H_DIM + h];
    v += fc_b[h];
    v = fmaxf(v, 0.0f);

    float p[4];
#pragma unroll
    for (int c = 0; c < 4; ++c) p[c] = v * out_w[c * H_DIM + h];

#pragma unroll
    for (int off = 16; off > 0; off >>= 1)
#pragma unroll
        for (int c = 0; c < 4; ++c) p[c] += __shfl_down_sync(0xffffffffu, p[c], off);

    __shared__ float red[4][16];
    if (lane == 0) {
#pragma unroll
        for (int c = 0; c < 4; ++c) red[c][wid] = p[c];
    }
    __syncthreads();
    if (h < 4) {
        float s = 0.0f;
#pragma unroll
        for (int w = 0; w < 16; ++w) s += red[h][w];
        out[b * C_OUT + h] = s + out_b[h];
    }
}

// ---------------------------------------------------------------------------
extern "C" void kernel_launch(void* const* d_in, const int* in_sizes, int n_in,
                              void* d_out, int out_size) {
    const float* x1     = (const float*)d_in[0];
    const float* x3     = (const float*)d_in[1];
    const float* conv_w = (const float*)d_in[2];
    const float* conv_b = (const float*)d_in[3];
    const float* bn_g   = (const float*)d_in[4];
    const float* bn_b   = (const float*)d_in[5];
    const float* bn_m   = (const float*)d_in[6];
    const float* bn_v   = (const float*)d_in[7];
    const float* fc_w   = (const float*)d_in[8];
    const float* fc_b   = (const float*)d_in[9];
    const float* out_w  = (const float*)d_in[10];
    const float* out_b  = (const float*)d_in[11];
    float* out = (float*)d_out;

    cudaFuncSetAttribute(gemm_kernel, cudaFuncAttributeMaxDynamicSharedMemorySize, SMEM_BYTES);

    prep_kernel<<<1, 32>>>(conv_w, conv_b, bn_g, bn_b, bn_m, bn_v);
    act_kernel<<<B_SZ * 2, 256>>>(x1, x3);
    dim3 grid(H_DIM / BN, SPLITS);
    gemm_kernel<<<grid, 512, SMEM_BYTES>>>(fc_w);
    head_kernel<<<B_SZ, 512>>>(fc_b, out_w, out_b, out);
}